// round 12
// baseline (speedup 1.0000x reference)
#include <cuda_runtime.h>
#include <cuda_fp16.h>
#include <math.h>
#include <stdint.h>

#define NN 50000
#define EE 800000
#define GG 32
#define DD 64
#define NT 256

// activation regions: [64 rows][72 el] fp16 single plane
#define R0 0
#define R1 9216
#define R2 18432
#define WBUF 27648
#define WSLOT 17408
#define B_BIAS 62464
#define B_IDX  63488
#define B_ACCG 64384
#define SMEM_REQ 72704

__device__ float g_nPost[NN*DD];
__device__ float g_sPost[GG*DD];
__device__ float g_accN[NN*DD];
__device__ int   g_cntN[NN];
__device__ float g_accEG[GG*DD]; __device__ int g_cntEG[GG];
__device__ float g_accNG[GG*DD]; __device__ int g_cntNG[GG];
__device__ float g_biasE0[GG*128];
__device__ float g_biasN0[GG*128];

#define WB_BE 0
#define WB_E0 4608
#define WB_E1 30720
#define WB_E2 48128
#define WB_N0 57344
#define WB_N1 74752
#define WB_N2 92160
#define W_TOT 101376
__device__ __align__(16) __half g_W[W_TOT];

__device__ __forceinline__ float sp(float x) {
    return fmaxf(x, 0.0f) + __logf(1.0f + __expf(-fabsf(x)));
}
__device__ __forceinline__ uint32_t su32(const void* p) {
    uint32_t a;
    asm("{ .reg .u64 t; cvta.to.shared.u64 t, %1; cvt.u32.u64 %0, t; }" : "=r"(a) : "l"(p));
    return a;
}
__device__ __forceinline__ void ldsm4(uint32_t* r, uint32_t a) {
    asm volatile("ldmatrix.sync.aligned.m8n8.x4.shared.b16 {%0,%1,%2,%3},[%4];"
        : "=r"(r[0]), "=r"(r[1]), "=r"(r[2]), "=r"(r[3]) : "r"(a));
}
__device__ __forceinline__ void ldsm4t(uint32_t* r, uint32_t a) {
    asm volatile("ldmatrix.sync.aligned.m8n8.x4.trans.shared.b16 {%0,%1,%2,%3},[%4];"
        : "=r"(r[0]), "=r"(r[1]), "=r"(r[2]), "=r"(r[3]) : "r"(a));
}
__device__ __forceinline__ void mma1(float* c, const uint32_t* a, uint32_t b0, uint32_t b1) {
    asm volatile("mma.sync.aligned.m16n8k16.row.col.f32.f16.f16.f32 "
        "{%0,%1,%2,%3},{%4,%5,%6,%7},{%8,%9},{%0,%1,%2,%3};"
        : "+f"(c[0]), "+f"(c[1]), "+f"(c[2]), "+f"(c[3])
        : "r"(a[0]), "r"(a[1]), "r"(a[2]), "r"(a[3]), "r"(b0), "r"(b1));
}
__device__ __forceinline__ void cp16(uint32_t d, const void* s) {
    asm volatile("cp.async.cg.shared.global [%0],[%1],16;" :: "r"(d), "l"(s));
}
__device__ __forceinline__ void cp_commit() { asm volatile("cp.async.commit_group;" ::: "memory"); }
__device__ __forceinline__ void cp_wait0() { asm volatile("cp.async.wait_group 0;" ::: "memory"); }

__device__ __forceinline__ void st72(char* base, int row, int k0, const float* v) {
    unsigned hu[4];
#pragma unroll
    for (int i = 0; i < 4; i++) {
        __half2 hb = __float22half2_rn(make_float2(v[2*i], v[2*i+1]));
        hu[i] = *reinterpret_cast<unsigned*>(&hb);
    }
    *(uint4*)(base + (row * 72 + k0) * 2) = make_uint4(hu[0], hu[1], hu[2], hu[3]);
}
__device__ __forceinline__ void gath16(const float* rp, char* base, int r, int k0, float scl) {
    float v[8];
#pragma unroll
    for (int s2 = 0; s2 < 2; s2++) {
        float4 a = __ldg((const float4*)(rp + k0 + s2*8));
        float4 b = __ldg((const float4*)(rp + k0 + s2*8 + 4));
        v[0]=a.x*scl; v[1]=a.y*scl; v[2]=a.z*scl; v[3]=a.w*scl;
        v[4]=b.x*scl; v[5]=b.y*scl; v[6]=b.z*scl; v[7]=b.w*scl;
        st72(base, r, k0 + s2*8, v);
    }
}
__device__ __forceinline__ void stageW(uint32_t sb, int el, int bpp, int slot, int t) {
    uint32_t dst = sb + WBUF + slot * WSLOT;
    const char* sh = (const char*)g_W + (size_t)el * 2;
    int nv = bpp >> 4;
    for (int i = t; i < nv; i += NT) cp16(dst + i*16, sh + i*16);
}

// 8 warps: warp tile 16 rows x N/2 cols. single-term fp16: C += A*W
template<int N>
__device__ __forceinline__ void mma_comp(uint32_t sb, int actR, int slot, float* C, int t) {
    const int NP = N + 8;
    const int nt = N / 32;
    int w = t >> 5, l = t & 31, lr = l & 15, lh = l >> 4;
    int wr = (w & 3) * 16, wc = (w >> 2) * (N / 2);
    uint32_t aB = sb + actR + (uint32_t)(((wr + lr) * 72 + lh * 8) * 2);
    uint32_t bB = sb + WBUF + slot * WSLOT + (uint32_t)((lr * NP + wc + lh * 8) * 2);
#pragma unroll
    for (int k16 = 0; k16 < 4; k16++) {
        uint32_t ah[4], bh[nt][4];
        ldsm4(ah, aB + k16 * 32);
#pragma unroll
        for (int n16 = 0; n16 < nt; n16++)
            ldsm4t(bh[n16], bB + (uint32_t)(k16 * 16 * NP * 2) + n16 * 32);
#pragma unroll
        for (int n16 = 0; n16 < nt; n16++) {
            float* c0 = C + n16 * 8;
            mma1(c0, ah, bh[n16][0], bh[n16][1]);
            mma1(c0 + 4, ah, bh[n16][2], bh[n16][3]);
        }
    }
}

template<int N, bool GB>
__device__ __forceinline__ void epi(char* sm, float* C, int t, int dA, int dB,
                                    const float* bias, const int* gix, const float* gbias) {
    const int nt = N / 32;
    int w = t >> 5, l = t & 31;
    int wr = (w & 3) * 16, wc = (w >> 2) * (N / 2);
    int lr = l >> 2, lc2 = 2 * (l & 3);
#pragma unroll
    for (int n16 = 0; n16 < nt; n16++)
#pragma unroll
    for (int nh = 0; nh < 2; nh++)
#pragma unroll
    for (int h = 0; h < 2; h++) {
        int row = wr + lr + h * 8;
        int col = wc + n16 * 16 + nh * 8 + lc2;
        float b0_, b1_;
        if (GB) {
            float2 bv = __ldg((const float2*)(gbias + gix[row] * 128 + col));
            b0_ = bv.x; b1_ = bv.y;
        } else { b0_ = bias[col]; b1_ = bias[col + 1]; }
        int ci = n16 * 8 + nh * 4 + h * 2;
        float v0 = sp(C[ci] + b0_), v1 = sp(C[ci + 1] + b1_);
        __half2 hb = __float22half2_rn(make_float2(v0, v1));
        char* p = sm + (col < 64 ? dA : dB) + (row * 72 + (col & 63)) * 2;
        *(uint32_t*)p = *(uint32_t*)&hb;
    }
}

__device__ __forceinline__ void finep(char* sm, float* C, int t, int mode, int tile0,
        const float* feat, float* outP, const int* dIdx, const int* gix,
        float* accG, int* cg, const float* b2s) {
    int w = t >> 5, l = t & 31;
    int wr = (w & 3) * 16, wc = (w >> 2) * 32;
    int lr = l >> 2, lc2 = 2 * (l & 3);
    float2 f[8];
    float bb[8];
#pragma unroll
    for (int n16 = 0; n16 < 2; n16++)
#pragma unroll
    for (int nh = 0; nh < 2; nh++)
#pragma unroll
    for (int h = 0; h < 2; h++) {
        int row = wr + lr + h * 8;
        int col = wc + n16 * 16 + nh * 8 + lc2;
        int grow = tile0 + row;
        int idx = n16 * 4 + nh * 2 + h;
        if (!mode || grow < NN)
            f[idx] = __ldg((const float2*)(feat + (size_t)grow * 64 + col));
        bb[idx] = b2s[col];
    }
#pragma unroll
    for (int n16 = 0; n16 < 2; n16++)
#pragma unroll
    for (int nh = 0; nh < 2; nh++)
#pragma unroll
    for (int h = 0; h < 2; h++) {
        int row = wr + lr + h * 8;
        int col = wc + n16 * 16 + nh * 8 + lc2;
        int grow = tile0 + row;
        if (mode && grow >= NN) continue;
        int idx = n16 * 4 + nh * 2 + h;
        int ci = n16 * 8 + nh * 4 + h * 2;
        float v0 = sp(C[ci] + bb[idx]), v1 = sp(C[ci + 1] + b2s[col + 1]);
        *(float2*)(outP + (size_t)grow * 64 + col) = make_float2(v0 + f[idx].x, v1 + f[idx].y);
        int g = gix[row];
        atomicAdd(accG + g * 65 + col, v0); atomicAdd(accG + g * 65 + col + 1, v1);
        if (mode == 0) {
            int d = dIdx[row];
            atomicAdd(g_accN + (size_t)d * 64 + col, v0);
            atomicAdd(g_accN + (size_t)d * 64 + col + 1, v1);
        }
        if ((w >> 2) == 0 && n16 == 0 && nh == 0 && (l & 3) == 0) {
            atomicAdd(cg + g, 1);
            if (mode == 0) atomicAdd(&g_cntN[dIdx[row]], 1);
        }
    }
}

__global__ __launch_bounds__(NT, 2) void k_mega(int mode, const float* __restrict__ feat,
        const int* __restrict__ srcI, const int* __restrict__ dstI, const int* __restrict__ batch,
        const float* __restrict__ beB, const float* __restrict__ b1e, const float* __restrict__ b2e,
        float* __restrict__ outP) {
    extern __shared__ char sm[];
    uint32_t sb = su32(sm);
    int t = threadIdx.x;
    int tile0 = blockIdx.x * 64;
    int* sIdx = (int*)(sm + B_IDX); int* dIdx = sIdx + 64; int* gix = dIdx + 64; int* cg = gix + 64;
    float* accG = (float*)(sm + B_ACCG);
    float* biasS = (float*)(sm + B_BIAS);
    const float* gbias = mode ? g_biasN0 : g_biasE0;

    int cel[8], cbp[8], nck;
    if (mode == 0) {
        cel[0]=WB_BE; cel[1]=WB_E0; cel[2]=WB_E0+8704; cel[3]=WB_E0+17408;
        cel[4]=WB_E1; cel[5]=WB_E1+8704; cel[6]=WB_E2; cel[7]=WB_E2+4608;
        cbp[0]=9216; cbp[1]=cbp[2]=cbp[3]=cbp[4]=cbp[5]=17408; cbp[6]=cbp[7]=9216;
        nck = 8;
    } else {
        cel[0]=WB_N0; cel[1]=WB_N0+8704; cel[2]=WB_N1; cel[3]=WB_N1+8704;
        cel[4]=WB_N2; cel[5]=WB_N2+4608;
        cbp[0]=cbp[1]=cbp[2]=cbp[3]=17408; cbp[4]=cbp[5]=9216;
        nck = 6;
    }
    stageW(sb, cel[0], cbp[0], 0, t);
    cp_commit();

    if (t < 64) biasS[t] = mode ? 0.f : __ldg(beB + t);
    else if (t < 192) biasS[t] = __ldg(b1e + t - 64);
    else biasS[t] = __ldg(b2e + t - 192);
    if (t < 64) {
        if (mode == 0) {
            int e = tile0 + t, s = srcI[e];
            sIdx[t] = s; dIdx[t] = dstI[e]; gix[t] = batch[s];
        } else gix[t] = batch[min(tile0 + t, NN - 1)];
    }
    for (int i = t; i < 2080; i += NT) accG[i] = 0.f;
    if (t < 32) cg[t] = 0;
    __syncthreads();
    {
        int r = t >> 2, k0 = (t & 3) * 16;
        if (mode == 0) {
            gath16(g_nPost + (size_t)sIdx[r] * 64, sm + R0, r, k0, 1.f);
            gath16(g_nPost + (size_t)dIdx[r] * 64, sm + R1, r, k0, 1.f);
            gath16(feat + (size_t)(tile0 + r) * 64, sm + R2, r, k0, 1.f);
        } else {
            int ni = min(tile0 + r, NN - 1);
            float inv = 1.f / fmaxf((float)g_cntN[ni], 1.f);
            gath16(g_nPost + (size_t)ni * 64, sm + R0, r, k0, 1.f);
            gath16(g_accN + (size_t)ni * 64, sm + R1, r, k0, inv);
        }
    }
    int ci = 0;
    float C[32];
#define STEP() do { cp_wait0(); __syncthreads(); \
        if (ci + 1 < nck) stageW(sb, cel[ci+1], cbp[ci+1], (ci+1) & 1, t); cp_commit(); } while (0)

    if (mode == 0) {
#pragma unroll
        for (int i = 0; i < 16; i++) C[i] = 0.f;
        STEP(); mma_comp<64>(sb, R2, 0, C, t); ci++;
        __syncthreads();
        epi<64,false>(sm, C, t, R2, R2, biasS, gix, gbias);
#pragma unroll
        for (int i = 0; i < 32; i++) C[i] = 0.f;
        const int ir0[3] = {R0, R1, R2};
        for (int c = 0; c < 3; c++) { STEP(); mma_comp<128>(sb, ir0[c], ci & 1, C, t); ci++; }
        __syncthreads();
        epi<128,true>(sm, C, t, R0, R1, biasS, gix, gbias);
    } else {
#pragma unroll
        for (int i = 0; i < 32; i++) C[i] = 0.f;
        const int ir0[2] = {R0, R1};
        for (int c = 0; c < 2; c++) { STEP(); mma_comp<128>(sb, ir0[c], ci & 1, C, t); ci++; }
        __syncthreads();
        epi<128,true>(sm, C, t, R0, R1, biasS, gix, gbias);
    }
#pragma unroll
    for (int i = 0; i < 32; i++) C[i] = 0.f;
    {
        const int ir1[2] = {R0, R1};
        for (int c = 0; c < 2; c++) { STEP(); mma_comp<128>(sb, ir1[c], ci & 1, C, t); ci++; }
    }
    __syncthreads();
    epi<128,false>(sm, C, t, R0, R1, biasS + 64, gix, gbias);
#pragma unroll
    for (int i = 0; i < 16; i++) C[i] = 0.f;
    {
        const int ir2[2] = {R0, R1};
        for (int c = 0; c < 2; c++) { STEP(); mma_comp<64>(sb, ir2[c], ci & 1, C, t); ci++; }
    }
    __syncthreads();
    finep(sm, C, t, mode, tile0, feat, outP, dIdx, gix, accG, cg, biasS + 192);
    __syncthreads();
    float* gacc = mode ? g_accNG : g_accEG;
    int* gcnt = mode ? g_cntNG : g_cntEG;
    for (int i = t; i < GG*DD; i += NT) atomicAdd(gacc + i, accG[(i >> 6) * 65 + (i & 63)]);
    if (t < 32) atomicAdd(gcnt + t, cg[t]);
#undef STEP
}

// ---------------- prep kernels ----------------
__global__ void k_prepAll(const float* beW, const float* e0, const float* e1, const float* e2,
                          const float* n0, const float* n1, const float* n2) {
    int tid = blockIdx.x * blockDim.x + threadIdx.x, st = gridDim.x * blockDim.x;
    for (int x = tid; x < NN*DD; x += st) g_accN[x] = 0.f;
    for (int x = tid; x < NN; x += st) g_cntN[x] = 0;
    for (int x = tid; x < GG*DD; x += st) { g_accEG[x] = 0.f; g_accNG[x] = 0.f; }
    for (int x = tid; x < GG; x += st) { g_cntEG[x] = 0; g_cntNG[x] = 0; }
    for (int x = tid; x < W_TOT; x += st) g_W[x] = __float2half(0.f);
    __threadfence();
    const float* S[7] = {beW, e0, e1, e2, n0, n1, n2};
    const int K[7] = {64, 192, 128, 128, 128, 128, 128};
    const int Nw[7] = {64, 128, 128, 64, 128, 128, 64};
    const int ba[7] = {WB_BE, WB_E0, WB_E1, WB_E2, WB_N0, WB_N1, WB_N2};
    for (int L = 0; L < 7; L++) {
        int KK = K[L], Nc = Nw[L], NP = Nc + 8;
        const float* Sp = S[L];
        for (int idx = tid; idx < KK * Nc; idx += st) {
            int k = idx / Nc, n = idx - k * Nc;
            int el = ba[L] + (k >> 6) * 64 * NP + (k & 63) * NP + n;
            g_W[el] = __float2half(Sp[idx]);
        }
    }
}
__global__ void k_spostBias(const float* __restrict__ sf, const float* __restrict__ W,
                            const float* __restrict__ b,
                            const float* ceW0, const float* ceB0,
                            const float* cnW0, const float* cnB0) {
    __shared__ float sP[GG*DD];
    int t = threadIdx.x;
    {
        int g = t >> 3, jb = (t & 7) * 8;
        float a[8];
#pragma unroll
        for (int u = 0; u < 8; u++) a[u] = __ldg(b + jb + u);
        for (int k = 0; k < 64; k++) {
            float x = __ldg(sf + g*64 + k);
#pragma unroll
            for (int u = 0; u < 8; u++) a[u] += x * __ldg(W + k*64 + jb + u);
        }
#pragma unroll
        for (int u = 0; u < 8; u++) { float v = sp(a[u]); sP[g*64+jb+u] = v; g_sPost[g*64+jb+u] = v; }
    }
    __syncthreads();
    for (int i = t; i < 2 * GG * 128; i += 256) {
        int tab = i >> 12, r = i & 4095;
        int g = r >> 7, f = r & 127;
        const float* Wp = tab ? cnW0 : ceW0;
        int koff = tab ? 128 : 192;
        float a = tab ? __ldg(cnB0 + f) : __ldg(ceB0 + f);
        for (int k = 0; k < 64; k++)
            a += sP[g*64 + k] * __ldg(Wp + (koff + k) * 128 + f);
        (tab ? g_biasN0 : g_biasE0)[r] = a;
    }
}
__global__ __launch_bounds__(256) void k_npost(const float* __restrict__ nf,
                                               const float* __restrict__ W, const float* __restrict__ b) {
    extern __shared__ float smf[];
    float* xN = smf; float* wS = smf + 8192;
    int t = threadIdx.x, n0 = blockIdx.x * 128;
    {
        int r = t >> 1, h = t & 1;
        int row = min(n0 + r, NN - 1);
        const float4* p = (const float4*)(nf + (size_t)row * 64) + h * 8;
#pragma unroll
        for (int i = 0; i < 8; i++) {
            float4 v = p[i]; int k = h * 32 + i * 4;
            xN[(k+0)*128+r]=v.x; xN[(k+1)*128+r]=v.y; xN[(k+2)*128+r]=v.z; xN[(k+3)*128+r]=v.w;
        }
    }
    for (int i = t * 4; i < 4096; i += 1024) *(float4*)(wS + i) = *(const float4*)(W + i);
    __syncthreads();
    int e = t & 127, half = t >> 7, j0 = half * 32;
    float a[32];
#pragma unroll
    for (int q = 0; q < 8; q++) {
        float4 bv = *(const float4*)(b + j0 + q*4);
        a[q*4+0]=bv.x; a[q*4+1]=bv.y; a[q*4+2]=bv.z; a[q*4+3]=bv.w;
    }
#pragma unroll 2
    for (int k = 0; k < 64; k++) {
        float x = xN[k*128 + e];
#pragma unroll
        for (int q = 0; q < 8; q++) {
            float4 wv = *(const float4*)(wS + k*64 + j0 + q*4);
            a[q*4+0]+=x*wv.x; a[q*4+1]+=x*wv.y; a[q*4+2]+=x*wv.z; a[q*4+3]+=x*wv.w;
        }
    }
    int row = n0 + e;
    if (row < NN) {
        float4* o = (float4*)(g_nPost + (size_t)row * 64 + j0);
#pragma unroll
        for (int q = 0; q < 8; q++)
            o[q] = make_float4(sp(a[q*4+0]), sp(a[q*4+1]), sp(a[q*4+2]), sp(a[q*4+3]));
    }
}
__global__ void k_state(const float* sf, const float* W0, const float* b0,
                        const float* W1, const float* b1, const float* W2, const float* b2, float* outS) {
    extern __shared__ float fs[];
    float* xs = fs; float* h1 = fs + 6144; float* hb = h1 + 4096;
    int t = threadIdx.x;
    for (int i = t; i < GG*DD; i += 256) {
        int g = i >> 6, k = i & 63;
        xs[g*192 + k] = g_sPost[i];
        xs[g*192 + 64 + k] = g_accEG[i] / fmaxf((float)g_cntEG[g], 1.f);
        xs[g*192 + 128 + k] = g_accNG[i] / fmaxf((float)g_cntNG[g], 1.f);
    }
    __syncthreads();
    for (int i = t; i < 4096; i += 256) {
        int g = i >> 7, f = i & 127;
        float a = __ldg(b0 + f);
        for (int k = 0; k < 192; k++) a += xs[g*192 + k] * __ldg(W0 + k*128 + f);
        h1[i] = sp(a);
    }
    __syncthreads();
    for (int i = t; i < 4096; i += 256) {
        int g = i >> 7, f = i & 127;
        float a = __ldg(b1 + f);
        for (int k = 0; k < 128; k++) a += h1[g*128 + k] * __ldg(W1 + k*128 + f);
        hb[i] = sp(a);
    }
    __syncthreads();
    for (int i = t; i < 2048; i += 256) {
        int g = i >> 6, f = i & 63;
        float a = __ldg(b2 + f);
        for (int k = 0; k < 128; k++) a += hb[g*128 + k] * __ldg(W2 + k*64 + f);
        outS[i] = sp(a) + __ldg(sf + i);
    }
}

extern "C" void kernel_launch(void* const* d_in, const int* in_sizes, int n_in,
                              void* d_out, int out_size) {
    const float* ef = (const float*)d_in[0];
    const float* nf = (const float*)d_in[1];
    const float* sf = (const float*)d_in[2];
    const int* eix = (const int*)d_in[3];
    const int* batch = (const int*)d_in[4];
    const float *beW=(const float*)d_in[5], *beB=(const float*)d_in[6];
    const float *bnW=(const float*)d_in[7], *bnB=(const float*)d_in[8];
    const float *bsW=(const float*)d_in[9], *bsB=(const float*)d_in[10];
    const float *ceW0=(const float*)d_in[11], *ceB0=(const float*)d_in[12];
    const float *ceW1=(const float*)d_in[13], *ceB1=(const float*)d_in[14];
    const float *ceW2=(const float*)d_in[15], *ceB2=(const float*)d_in[16];
    const float *cnW0=(const float*)d_in[17], *cnB0=(const float*)d_in[18];
    const float *cnW1=(const float*)d_in[19], *cnB1=(const float*)d_in[20];
    const float *cnW2=(const float*)d_in[21], *cnB2=(const float*)d_in[22];
    const float *csW0=(const float*)d_in[23], *csB0=(const float*)d_in[24];
    const float *csW1=(const float*)d_in[25], *csB1=(const float*)d_in[26];
    const float *csW2=(const float*)d_in[27], *csB2=(const float*)d_in[28];
    const int* srcI = eix; const int* dstI = eix + EE;
    float* outE = (float*)d_out;
    float* outN = outE + (size_t)EE * 64;
    float* outS = outN + (size_t)NN * 64;

    size_t smNP = (8192 + 4096) * sizeof(float);
    cudaFuncSetAttribute(k_npost, cudaFuncAttributeMaxDynamicSharedMemorySize, (int)smNP);
    cudaFuncSetAttribute(k_mega, cudaFuncAttributeMaxDynamicSharedMemorySize, SMEM_REQ);
    cudaFuncSetAttribute(k_state, cudaFuncAttributeMaxDynamicSharedMemorySize, 57344);

    k_prepAll<<<512, 512>>>(beW, ceW0, ceW1, ceW2, cnW0, cnW1, cnW2);
    k_spostBias<<<1, 256>>>(sf, bsW, bsB, ceW0, ceB0, cnW0, cnB0);
    k_npost<<<(NN + 127) / 128, 256, smNP>>>(nf, bnW, bnB);
    k_mega<<<EE / 64, NT, SMEM_REQ>>>(0, ef, srcI, dstI, batch, beB, ceB1, ceB2, outE);
    k_mega<<<(NN + 63) / 64, NT, SMEM_REQ>>>(1, nf, srcI, dstI, batch, beB, cnB1, cnB2, outN);
    k_state<<<1, 256, 57344>>>(sf, csW0, csB0, csW1, csB1, csW2, csB2, outS);
}

// round 13
// speedup vs baseline: 1.4521x; 1.4521x over previous
#include <cuda_runtime.h>
#include <cuda_fp16.h>
#include <math.h>
#include <stdint.h>

#define NN 50000
#define EE 800000
#define GG 32
#define DD 64
#define NT 256

// activation regions: [64 rows][72 el] fp16 hi plane + lo plane (+PL bytes)
#define PL  9216
#define R0 0
#define R1 18432
#define R2 36864
#define B_BIAS 55296
#define B_IDX  56320
#define B_ACCG 57216
#define SMEM_REQ 65536

__device__ float g_nPost[NN*DD];
__device__ float g_sPost[GG*DD];
__device__ float g_accN[NN*DD];
__device__ int   g_cntN[NN];
__device__ float g_accEG[GG*DD]; __device__ int g_cntEG[GG];
__device__ float g_accNG[GG*DD]; __device__ int g_cntNG[GG];
__device__ float g_biasE0[GG*128];
__device__ float g_biasN0[GG*128];

// fragment-packed weights: per layer, chunks of K=64; per chunk
// [k16:4][n16:N/16][lane:32] x uint4 (= documented m16n8k16 B fragment order)
#define W_TOT 94208
__device__ __align__(16) __half g_Wfrag[W_TOT];

__device__ __forceinline__ float sp(float x) {
    return fmaxf(x, 0.0f) + __logf(1.0f + __expf(-fabsf(x)));
}
__device__ __forceinline__ uint32_t su32(const void* p) {
    uint32_t a;
    asm("{ .reg .u64 t; cvta.to.shared.u64 t, %1; cvt.u32.u64 %0, t; }" : "=r"(a) : "l"(p));
    return a;
}
__device__ __forceinline__ void ldsm4(uint32_t* r, uint32_t a) {
    asm volatile("ldmatrix.sync.aligned.m8n8.x4.shared.b16 {%0,%1,%2,%3},[%4];"
        : "=r"(r[0]), "=r"(r[1]), "=r"(r[2]), "=r"(r[3]) : "r"(a));
}
__device__ __forceinline__ void mma1(float* c, const uint32_t* a, uint32_t b0, uint32_t b1) {
    asm volatile("mma.sync.aligned.m16n8k16.row.col.f32.f16.f16.f32 "
        "{%0,%1,%2,%3},{%4,%5,%6,%7},{%8,%9},{%0,%1,%2,%3};"
        : "+f"(c[0]), "+f"(c[1]), "+f"(c[2]), "+f"(c[3])
        : "r"(a[0]), "r"(a[1]), "r"(a[2]), "r"(a[3]), "r"(b0), "r"(b1));
}

__device__ __forceinline__ void st72(char* base, int row, int k0, const float* v) {
    unsigned hu[4], lu[4];
#pragma unroll
    for (int i = 0; i < 4; i++) {
        float2 p = make_float2(v[2*i], v[2*i+1]);
        __half2 hb = __float22half2_rn(p);
        float2 hf = __half22float2(hb);
        __half2 lb = __float22half2_rn(make_float2(p.x - hf.x, p.y - hf.y));
        hu[i] = *reinterpret_cast<unsigned*>(&hb);
        lu[i] = *reinterpret_cast<unsigned*>(&lb);
    }
    int bo = (row * 72 + k0) * 2;
    *(uint4*)(base + bo) = make_uint4(hu[0], hu[1], hu[2], hu[3]);
    *(uint4*)(base + PL + bo) = make_uint4(lu[0], lu[1], lu[2], lu[3]);
}
__device__ __forceinline__ void gath16(const float* rp, char* base, int r, int k0, float scl) {
    float v[8];
#pragma unroll
    for (int s2 = 0; s2 < 2; s2++) {
        float4 a = __ldg((const float4*)(rp + k0 + s2*8));
        float4 b = __ldg((const float4*)(rp + k0 + s2*8 + 4));
        v[0]=a.x*scl; v[1]=a.y*scl; v[2]=a.z*scl; v[3]=a.w*scl;
        v[4]=b.x*scl; v[5]=b.y*scl; v[6]=b.z*scl; v[7]=b.w*scl;
        st72(base, r, k0 + s2*8, v);
    }
}

// 8 warps: warp tile 16 rows x N/2 cols. fp16 2-term: C += Ah*W + Al*W
// B fragments loaded directly from global (L1-cached), pre-packed in mma order.
template<int N>
__device__ __forceinline__ void mma_comp(uint32_t sb, int actR, const __half* wf, float* C, int t) {
    const int nt = N / 32;
    int w = t >> 5, l = t & 31, lr = l & 15, lh = l >> 4;
    int wr = (w & 3) * 16, wcg = w >> 2;
    uint32_t aB = sb + actR + (uint32_t)(((wr + lr) * 72 + lh * 8) * 2);
    const uint4* wfb = (const uint4*)wf + (size_t)(wcg * nt) * 32 + l;
#pragma unroll
    for (int k16 = 0; k16 < 4; k16++) {
        uint4 bh[nt];
#pragma unroll
        for (int n16 = 0; n16 < nt; n16++)
            bh[n16] = __ldg(wfb + (size_t)(k16 * (N / 16) + n16) * 32);
        uint32_t ah[4], al[4];
        ldsm4(ah, aB + k16 * 32);
        ldsm4(al, aB + k16 * 32 + PL);
#pragma unroll
        for (int n16 = 0; n16 < nt; n16++) {
            float* c0 = C + n16 * 8;
            mma1(c0, ah, bh[n16].x, bh[n16].y);
            mma1(c0 + 4, ah, bh[n16].z, bh[n16].w);
        }
#pragma unroll
        for (int n16 = 0; n16 < nt; n16++) {
            float* c0 = C + n16 * 8;
            mma1(c0, al, bh[n16].x, bh[n16].y);
            mma1(c0 + 4, al, bh[n16].z, bh[n16].w);
        }
    }
}

template<int N, bool GB>
__device__ __forceinline__ void epi(char* sm, float* C, int t, int dA, int dB,
                                    const float* bias, const int* gix, const float* gbias) {
    const int nt = N / 32;
    int w = t >> 5, l = t & 31;
    int wr = (w & 3) * 16, wc = (w >> 2) * (N / 2);
    int lr = l >> 2, lc2 = 2 * (l & 3);
#pragma unroll
    for (int n16 = 0; n16 < nt; n16++)
#pragma unroll
    for (int nh = 0; nh < 2; nh++)
#pragma unroll
    for (int h = 0; h < 2; h++) {
        int row = wr + lr + h * 8;
        int col = wc + n16 * 16 + nh * 8 + lc2;
        float b0_, b1_;
        if (GB) {
            float2 bv = __ldg((const float2*)(gbias + gix[row] * 128 + col));
            b0_ = bv.x; b1_ = bv.y;
        } else { b0_ = bias[col]; b1_ = bias[col + 1]; }
        int ci = n16 * 8 + nh * 4 + h * 2;
        float v0 = sp(C[ci] + b0_), v1 = sp(C[ci + 1] + b1_);
        __half2 hb = __float22half2_rn(make_float2(v0, v1));
        float2 hf = __half22float2(hb);
        __half2 lb = __float22half2_rn(make_float2(v0 - hf.x, v1 - hf.y));
        char* p = sm + (col < 64 ? dA : dB) + (row * 72 + (col & 63)) * 2;
        *(uint32_t*)p = *(uint32_t*)&hb;
        *(uint32_t*)(p + PL) = *(uint32_t*)&lb;
    }
}

__device__ __forceinline__ void finep(char* sm, float* C, int t, int mode, int tile0,
        const float* feat, float* outP, const int* dIdx, const int* gix,
        float* accG, int* cg, const float* b2s) {
    int w = t >> 5, l = t & 31;
    int wr = (w & 3) * 16, wc = (w >> 2) * 32;
    int lr = l >> 2, lc2 = 2 * (l & 3);
    float2 f[8];
    float bb[8];
#pragma unroll
    for (int n16 = 0; n16 < 2; n16++)
#pragma unroll
    for (int nh = 0; nh < 2; nh++)
#pragma unroll
    for (int h = 0; h < 2; h++) {
        int row = wr + lr + h * 8;
        int col = wc + n16 * 16 + nh * 8 + lc2;
        int grow = tile0 + row;
        int idx = n16 * 4 + nh * 2 + h;
        if (!mode || grow < NN)
            f[idx] = __ldg((const float2*)(feat + (size_t)grow * 64 + col));
        bb[idx] = b2s[col];
    }
#pragma unroll
    for (int n16 = 0; n16 < 2; n16++)
#pragma unroll
    for (int nh = 0; nh < 2; nh++)
#pragma unroll
    for (int h = 0; h < 2; h++) {
        int row = wr + lr + h * 8;
        int col = wc + n16 * 16 + nh * 8 + lc2;
        int grow = tile0 + row;
        if (mode && grow >= NN) continue;
        int idx = n16 * 4 + nh * 2 + h;
        int ci = n16 * 8 + nh * 4 + h * 2;
        float v0 = sp(C[ci] + bb[idx]), v1 = sp(C[ci + 1] + b2s[col + 1]);
        *(float2*)(outP + (size_t)grow * 64 + col) = make_float2(v0 + f[idx].x, v1 + f[idx].y);
        int g = gix[row];
        atomicAdd(accG + g * 65 + col, v0); atomicAdd(accG + g * 65 + col + 1, v1);
        if (mode == 0) {
            int d = dIdx[row];
            atomicAdd(g_accN + (size_t)d * 64 + col, v0);
            atomicAdd(g_accN + (size_t)d * 64 + col + 1, v1);
        }
        if ((w >> 2) == 0 && n16 == 0 && nh == 0 && (l & 3) == 0) {
            atomicAdd(cg + g, 1);
            if (mode == 0) atomicAdd(&g_cntN[dIdx[row]], 1);
        }
    }
}

__global__ __launch_bounds__(NT, 2) void k_mega(int mode, const float* __restrict__ feat,
        const int* __restrict__ srcI, const int* __restrict__ dstI, const int* __restrict__ batch,
        const float* __restrict__ beB, const float* __restrict__ b1e, const float* __restrict__ b2e,
        float* __restrict__ outP) {
    extern __shared__ char sm[];
    uint32_t sb = su32(sm);
    int t = threadIdx.x;
    int tile0 = blockIdx.x * 64;
    int* sIdx = (int*)(sm + B_IDX); int* dIdx = sIdx + 64; int* gix = dIdx + 64; int* cg = gix + 64;
    float* accG = (float*)(sm + B_ACCG);
    float* biasS = (float*)(sm + B_BIAS);
    const float* gbias = mode ? g_biasN0 : g_biasE0;

    if (t < 64) biasS[t] = mode ? 0.f : __ldg(beB + t);
    else if (t < 192) biasS[t] = __ldg(b1e + t - 64);
    else biasS[t] = __ldg(b2e + t - 192);
    if (t < 64) {
        if (mode == 0) {
            int e = tile0 + t, s = srcI[e];
            sIdx[t] = s; dIdx[t] = dstI[e]; gix[t] = batch[s];
        } else gix[t] = batch[min(tile0 + t, NN - 1)];
    }
    for (int i = t; i < 2080; i += NT) accG[i] = 0.f;
    if (t < 32) cg[t] = 0;
    __syncthreads();
    {
        int r = t >> 2, k0 = (t & 3) * 16;
        if (mode == 0) {
            gath16(g_nPost + (size_t)sIdx[r] * 64, sm + R0, r, k0, 1.f);
            gath16(g_nPost + (size_t)dIdx[r] * 64, sm + R1, r, k0, 1.f);
            gath16(feat + (size_t)(tile0 + r) * 64, sm + R2, r, k0, 1.f);
        } else {
            int ni = min(tile0 + r, NN - 1);
            float inv = 1.f / fmaxf((float)g_cntN[ni], 1.f);
            gath16(g_nPost + (size_t)ni * 64, sm + R0, r, k0, 1.f);
            gath16(g_accN + (size_t)ni * 64, sm + R1, r, k0, inv);
        }
    }
    __syncthreads();
    float C[32];
    const __half* WF = g_Wfrag;
    if (mode == 0) {
#pragma unroll
        for (int i = 0; i < 16; i++) C[i] = 0.f;
        mma_comp<64>(sb, R2, WF + 0, C, t);
        __syncthreads();
        epi<64,false>(sm, C, t, R2, R2, biasS, gix, gbias);
        __syncthreads();
#pragma unroll
        for (int i = 0; i < 32; i++) C[i] = 0.f;
        mma_comp<128>(sb, R0, WF + 4096, C, t);
        mma_comp<128>(sb, R1, WF + 12288, C, t);
        mma_comp<128>(sb, R2, WF + 20480, C, t);
        __syncthreads();
        epi<128,true>(sm, C, t, R0, R1, biasS, gix, gbias);
        __syncthreads();
#pragma unroll
        for (int i = 0; i < 32; i++) C[i] = 0.f;
        mma_comp<128>(sb, R0, WF + 28672, C, t);
        mma_comp<128>(sb, R1, WF + 36864, C, t);
        __syncthreads();
        epi<128,false>(sm, C, t, R0, R1, biasS + 64, gix, gbias);
        __syncthreads();
#pragma unroll
        for (int i = 0; i < 16; i++) C[i] = 0.f;
        mma_comp<64>(sb, R0, WF + 45056, C, t);
        mma_comp<64>(sb, R1, WF + 49152, C, t);
    } else {
#pragma unroll
        for (int i = 0; i < 32; i++) C[i] = 0.f;
        mma_comp<128>(sb, R0, WF + 53248, C, t);
        mma_comp<128>(sb, R1, WF + 61440, C, t);
        __syncthreads();
        epi<128,true>(sm, C, t, R0, R1, biasS, gix, gbias);
        __syncthreads();
#pragma unroll
        for (int i = 0; i < 32; i++) C[i] = 0.f;
        mma_comp<128>(sb, R0, WF + 69632, C, t);
        mma_comp<128>(sb, R1, WF + 77824, C, t);
        __syncthreads();
        epi<128,false>(sm, C, t, R0, R1, biasS + 64, gix, gbias);
        __syncthreads();
#pragma unroll
        for (int i = 0; i < 16; i++) C[i] = 0.f;
        mma_comp<64>(sb, R0, WF + 86016, C, t);
        mma_comp<64>(sb, R1, WF + 90112, C, t);
    }
    __syncthreads();
    finep(sm, C, t, mode, tile0, feat, outP, dIdx, gix, accG, cg, biasS + 192);
    __syncthreads();
    float* gacc = mode ? g_accNG : g_accEG;
    int* gcnt = mode ? g_cntNG : g_cntEG;
    for (int i = t; i < GG*DD; i += NT) atomicAdd(gacc + i, accG[(i >> 6) * 65 + (i & 63)]);
    if (t < 32) atomicAdd(gcnt + t, cg[t]);
}

// ---------------- prep kernels ----------------
__global__ void k_prepAll(const float* beW, const float* e0, const float* e1, const float* e2,
                          const float* n0, const float* n1, const float* n2) {
    int tid = blockIdx.x * blockDim.x + threadIdx.x, st = gridDim.x * blockDim.x;
    for (int x = tid; x < NN*DD; x += st) g_accN[x] = 0.f;
    for (int x = tid; x < NN; x += st) g_cntN[x] = 0;
    for (int x = tid; x < GG*DD; x += st) { g_accEG[x] = 0.f; g_accNG[x] = 0.f; }
    for (int x = tid; x < GG; x += st) { g_cntEG[x] = 0; g_cntNG[x] = 0; }
    const float* S[7] = {beW, e0, e1, e2, n0, n1, n2};
    const int K[7] = {64, 192, 128, 128, 128, 128, 128};
    const int Nw[7] = {64, 128, 128, 64, 128, 128, 64};
    const int ba[7] = {0, 4096, 28672, 45056, 53248, 69632, 86016};
    for (int L = 0; L < 7; L++) {
        int KK = K[L], Nc = Nw[L];
        const float* Sp = S[L];
        for (int idx = tid; idx < KK * Nc; idx += st) {
            int c = idx / (64 * Nc);
            int rch = idx - c * 64 * Nc;
            int f = rch >> 8;               // fragment = i*(Nc/16)+j
            int wi = rch & 255;
            int l = wi >> 3;
            int r = (wi >> 1) & 3;
            int q = wi & 1;
            int i = f / (Nc / 16), j = f - i * (Nc / 16);
            int k = c * 64 + i * 16 + 2 * (l & 3) + (r & 1) * 8 + q;
            int n = j * 16 + (r >> 1) * 8 + (l >> 2);
            g_Wfrag[ba[L] + idx] = __float2half(Sp[k * Nc + n]);
        }
    }
}
__global__ void k_spostBias(const float* __restrict__ sf, const float* __restrict__ W,
                            const float* __restrict__ b,
                            const float* ceW0, const float* ceB0,
                            const float* cnW0, const float* cnB0) {
    __shared__ float sP[GG*DD];
    int t = threadIdx.x;
    {
        int g = t >> 3, jb = (t & 7) * 8;
        float a[8];
#pragma unroll
        for (int u = 0; u < 8; u++) a[u] = __ldg(b + jb + u);
        for (int k = 0; k < 64; k++) {
            float x = __ldg(sf + g*64 + k);
#pragma unroll
            for (int u = 0; u < 8; u++) a[u] += x * __ldg(W + k*64 + jb + u);
        }
#pragma unroll
        for (int u = 0; u < 8; u++) { float v = sp(a[u]); sP[g*64+jb+u] = v; g_sPost[g*64+jb+u] = v; }
    }
    __syncthreads();
    for (int i = t; i < 2 * GG * 128; i += 256) {
        int tab = i >> 12, r = i & 4095;
        int g = r >> 7, f = r & 127;
        const float* Wp = tab ? cnW0 : ceW0;
        int koff = tab ? 128 : 192;
        float a = tab ? __ldg(cnB0 + f) : __ldg(ceB0 + f);
        for (int k = 0; k < 64; k++)
            a += sP[g*64 + k] * __ldg(Wp + (koff + k) * 128 + f);
        (tab ? g_biasN0 : g_biasE0)[r] = a;
    }
}
__global__ __launch_bounds__(256) void k_npost(const float* __restrict__ nf,
                                               const float* __restrict__ W, const float* __restrict__ b) {
    extern __shared__ float smf[];
    float* xN = smf; float* wS = smf + 8192;
    int t = threadIdx.x, n0 = blockIdx.x * 128;
    {
        int r = t >> 1, h = t & 1;
        int row = min(n0 + r, NN - 1);
        const float4* p = (const float4*)(nf + (size_t)row * 64) + h * 8;
#pragma unroll
        for (int i = 0; i < 8; i++) {
            float4 v = p[i]; int k = h * 32 + i * 4;
            xN[(k+0)*128+r]=v.x; xN[(k+1)*128+r]=v.y; xN[(k+2)*128+r]=v.z; xN[(k+3)*128+r]=v.w;
        }
    }
    for (int i = t * 4; i < 4096; i += 1024) *(float4*)(wS + i) = *(const float4*)(W + i);
    __syncthreads();
    int e = t & 127, half = t >> 7, j0 = half * 32;
    float a[32];
#pragma unroll
    for (int q = 0; q < 8; q++) {
        float4 bv = *(const float4*)(b + j0 + q*4);
        a[q*4+0]=bv.x; a[q*4+1]=bv.y; a[q*4+2]=bv.z; a[q*4+3]=bv.w;
    }
#pragma unroll 2
    for (int k = 0; k < 64; k++) {
        float x = xN[k*128 + e];
#pragma unroll
        for (int q = 0; q < 8; q++) {
            float4 wv = *(const float4*)(wS + k*64 + j0 + q*4);
            a[q*4+0]+=x*wv.x; a[q*4+1]+=x*wv.y; a[q*4+2]+=x*wv.z; a[q*4+3]+=x*wv.w;
        }
    }
    int row = n0 + e;
    if (row < NN) {
        float4* o = (float4*)(g_nPost + (size_t)row * 64 + j0);
#pragma unroll
        for (int q = 0; q < 8; q++)
            o[q] = make_float4(sp(a[q*4+0]), sp(a[q*4+1]), sp(a[q*4+2]), sp(a[q*4+3]));
    }
}
__global__ void k_state(const float* sf, const float* W0, const float* b0,
                        const float* W1, const float* b1, const float* W2, const float* b2, float* outS) {
    extern __shared__ float fs[];
    float* xs = fs; float* h1 = fs + 6144; float* hb = h1 + 4096;
    int t = threadIdx.x;
    for (int i = t; i < GG*DD; i += 256) {
        int g = i >> 6, k = i & 63;
        xs[g*192 + k] = g_sPost[i];
        xs[g*192 + 64 + k] = g_accEG[i] / fmaxf((float)g_cntEG[g], 1.f);
        xs[g*192 + 128 + k] = g_accNG[i] / fmaxf((float)g_cntNG[g], 1.f);
    }
    __syncthreads();
    for (int i = t; i < 4096; i += 256) {
        int g = i >> 7, f = i & 127;
        float a = __ldg(b0 + f);
        for (int k = 0; k < 192; k++) a += xs[g*192 + k] * __ldg(W0 + k*128 + f);
        h1[i] = sp(a);
    }
    __syncthreads();
    for (int i = t; i < 4096; i += 256) {
        int g = i >> 7, f = i & 127;
        float a = __ldg(b1 + f);
        for (int k = 0; k < 128; k++) a += h1[g*128 + k] * __ldg(W1 + k*128 + f);
        hb[i] = sp(a);
    }
    __syncthreads();
    for (int i = t; i < 2048; i += 256) {
        int g = i >> 6, f = i & 63;
        float a = __ldg(b2 + f);
        for (int k = 0; k < 128; k++) a += hb[g*128 + k] * __ldg(W2 + k*64 + f);
        outS[i] = sp(a) + __ldg(sf + i);
    }
}

extern "C" void kernel_launch(void* const* d_in, const int* in_sizes, int n_in,
                              void* d_out, int out_size) {
    const float* ef = (const float*)d_in[0];
    const float* nf = (const float*)d_in[1];
    const float* sf = (const float*)d_in[2];
    const int* eix = (const int*)d_in[3];
    const int* batch = (const int*)d_in[4];
    const float *beW=(const float*)d_in[5], *beB=(const float*)d_in[6];
    const float *bnW=(const float*)d_in[7], *bnB=(const float*)d_in[8];
    const float *bsW=(const float*)d_in[9], *bsB=(const float*)d_in[10];
    const float *ceW0=(const float*)d_in[11], *ceB0=(const float*)d_in[12];
    const float *ceW1=(const float*)d_in[13], *ceB1=(const float*)d_in[14];
    const float *ceW2=(const float*)d_in[15], *ceB2=(const float*)d_in[16];
    const float *cnW0=(const float*)d_in[17], *cnB0=(const float*)d_in[18];
    const float *cnW1=(const float*)d_in[19], *cnB1=(const float*)d_in[20];
    const float *cnW2=(const float*)d_in[21], *cnB2=(const float*)d_in[22];
    const float *csW0=(const float*)d_in[23], *csB0=(const float*)d_in[24];
    const float *csW1=(const float*)d_in[25], *csB1=(const float*)d_in[26];
    const float *csW2=(const float*)d_in[27], *csB2=(const float*)d_in[28];
    const int* srcI = eix; const int* dstI = eix + EE;
    float* outE = (float*)d_out;
    float* outN = outE + (size_t)EE * 64;
    float* outS = outN + (size_t)NN * 64;

    size_t smNP = (8192 + 4096) * sizeof(float);
    cudaFuncSetAttribute(k_npost, cudaFuncAttributeMaxDynamicSharedMemorySize, (int)smNP);
    cudaFuncSetAttribute(k_mega, cudaFuncAttributeMaxDynamicSharedMemorySize, SMEM_REQ);
    cudaFuncSetAttribute(k_state, cudaFuncAttributeMaxDynamicSharedMemorySize, 57344);

    k_prepAll<<<512, 512>>>(beW, ceW0, ceW1, ceW2, cnW0, cnW1, cnW2);
    k_spostBias<<<1, 256>>>(sf, bsW, bsB, ceW0, ceB0, cnW0, cnB0);
    k_npost<<<(NN + 127) / 128, 256, smNP>>>(nf, bnW, bnB);
    k_mega<<<EE / 64, NT, SMEM_REQ>>>(0, ef, srcI, dstI, batch, beB, ceB1, ceB2, outE);
    k_mega<<<(NN + 63) / 64, NT, SMEM_REQ>>>(1, nf, srcI, dstI, batch, beB, cnB1, cnB2, outN);
    k_state<<<1, 256, 57344>>>(sf, csW0, csB0, csW1, csB1, csW2, csB2, outS);
}

// round 14
// speedup vs baseline: 1.4732x; 1.0145x over previous
#include <cuda_runtime.h>
#include <cuda_fp16.h>
#include <math.h>
#include <stdint.h>

#define NN 50000
#define EE 800000
#define GG 32
#define DD 64
#define NT 256

// activation regions: [64 rows][72 el] fp16 hi plane + lo plane (+PL bytes)
#define PL  9216
#define R0 0
#define R1 18432
#define R2 36864
#define B_BIAS 55296
#define B_IDX  56320
#define B_ACCG 57216
#define SMEM_REQ 65536

__device__ __half g_nPH[NN*DD];   // nPost hi plane (fp16)
__device__ __half g_nPL[NN*DD];   // nPost lo plane (fp16 residual)
__device__ float g_sPost[GG*DD];
__device__ float g_accN[NN*DD];
__device__ int   g_cntN[NN];
__device__ float g_accEG[GG*DD]; __device__ int g_cntEG[GG];
__device__ float g_accNG[GG*DD]; __device__ int g_cntNG[GG];
__device__ float g_biasE0[GG*128];
__device__ float g_biasN0[GG*128];

// fragment-packed weights: per layer, chunks of K=64; per chunk
// [k16:4][n16:N/16][lane:32] x uint4 (= documented m16n8k16 B fragment order)
#define W_TOT 94208
__device__ __align__(16) __half g_Wfrag[W_TOT];

__device__ __forceinline__ float sp(float x) {
    return fmaxf(x, 0.0f) + __logf(1.0f + __expf(-fabsf(x)));
}
__device__ __forceinline__ uint32_t su32(const void* p) {
    uint32_t a;
    asm("{ .reg .u64 t; cvta.to.shared.u64 t, %1; cvt.u32.u64 %0, t; }" : "=r"(a) : "l"(p));
    return a;
}
__device__ __forceinline__ void ldsm4(uint32_t* r, uint32_t a) {
    asm volatile("ldmatrix.sync.aligned.m8n8.x4.shared.b16 {%0,%1,%2,%3},[%4];"
        : "=r"(r[0]), "=r"(r[1]), "=r"(r[2]), "=r"(r[3]) : "r"(a));
}
__device__ __forceinline__ void mma1(float* c, const uint32_t* a, uint32_t b0, uint32_t b1) {
    asm volatile("mma.sync.aligned.m16n8k16.row.col.f32.f16.f16.f32 "
        "{%0,%1,%2,%3},{%4,%5,%6,%7},{%8,%9},{%0,%1,%2,%3};"
        : "+f"(c[0]), "+f"(c[1]), "+f"(c[2]), "+f"(c[3])
        : "r"(a[0]), "r"(a[1]), "r"(a[2]), "r"(a[3]), "r"(b0), "r"(b1));
}
__device__ __forceinline__ void cp16(uint32_t d, const void* s) {
    asm volatile("cp.async.cg.shared.global [%0],[%1],16;" :: "r"(d), "l"(s));
}
__device__ __forceinline__ void cp_commit() { asm volatile("cp.async.commit_group;" ::: "memory"); }
__device__ __forceinline__ void cp_wait0() { asm volatile("cp.async.wait_group 0;" ::: "memory"); }
__device__ __forceinline__ void redv2(float* p, float v0, float v1) {
    asm volatile("red.global.add.v2.f32 [%0], {%1,%2};" :: "l"(p), "f"(v0), "f"(v1) : "memory");
}

__device__ __forceinline__ void st72(char* base, int row, int k0, const float* v) {
    unsigned hu[4], lu[4];
#pragma unroll
    for (int i = 0; i < 4; i++) {
        float2 p = make_float2(v[2*i], v[2*i+1]);
        __half2 hb = __float22half2_rn(p);
        float2 hf = __half22float2(hb);
        __half2 lb = __float22half2_rn(make_float2(p.x - hf.x, p.y - hf.y));
        hu[i] = *reinterpret_cast<unsigned*>(&hb);
        lu[i] = *reinterpret_cast<unsigned*>(&lb);
    }
    int bo = (row * 72 + k0) * 2;
    *(uint4*)(base + bo) = make_uint4(hu[0], hu[1], hu[2], hu[3]);
    *(uint4*)(base + PL + bo) = make_uint4(lu[0], lu[1], lu[2], lu[3]);
}
__device__ __forceinline__ void gath16(const float* rp, char* base, int r, int k0, float scl) {
    float v[8];
#pragma unroll
    for (int s2 = 0; s2 < 2; s2++) {
        float4 a = __ldg((const float4*)(rp + k0 + s2*8));
        float4 b = __ldg((const float4*)(rp + k0 + s2*8 + 4));
        v[0]=a.x*scl; v[1]=a.y*scl; v[2]=a.z*scl; v[3]=a.w*scl;
        v[4]=b.x*scl; v[5]=b.y*scl; v[6]=b.z*scl; v[7]=b.w*scl;
        st72(base, r, k0 + s2*8, v);
    }
}
// split-plane gather: 16 fp16 els from each plane via cp.async (no reg round-trip)
__device__ __forceinline__ void gathSplit(uint32_t sb, int reg, int row, int r, int k0) {
    const __half* ph = g_nPH + (size_t)row * 64 + k0;
    const __half* pl = g_nPL + (size_t)row * 64 + k0;
    uint32_t d = sb + reg + (uint32_t)((r * 72 + k0) * 2);
    cp16(d, ph); cp16(d + 16, ph + 8);
    cp16(d + PL, pl); cp16(d + PL + 16, pl + 8);
}

// 8 warps: warp tile 16 rows x N/2 cols. fp16 2-term: C += Ah*W + Al*W
// B fragments loaded directly from global (L1-cached), pre-packed in mma order.
template<int N>
__device__ __forceinline__ void mma_comp(uint32_t sb, int actR, const __half* wf, float* C, int t) {
    const int nt = N / 32;
    int w = t >> 5, l = t & 31, lr = l & 15, lh = l >> 4;
    int wr = (w & 3) * 16, wcg = w >> 2;
    uint32_t aB = sb + actR + (uint32_t)(((wr + lr) * 72 + lh * 8) * 2);
    const uint4* wfb = (const uint4*)wf + (wcg * nt) * 32 + l;
#pragma unroll
    for (int k16 = 0; k16 < 4; k16++) {
        uint4 bh[nt];
#pragma unroll
        for (int n16 = 0; n16 < nt; n16++)
            bh[n16] = __ldg(wfb + (k16 * (N / 16) + n16) * 32);
        uint32_t ah[4], al[4];
        ldsm4(ah, aB + k16 * 32);
        ldsm4(al, aB + k16 * 32 + PL);
#pragma unroll
        for (int n16 = 0; n16 < nt; n16++) {
            float* c0 = C + n16 * 8;
            mma1(c0, ah, bh[n16].x, bh[n16].y);
            mma1(c0 + 4, ah, bh[n16].z, bh[n16].w);
        }
#pragma unroll
        for (int n16 = 0; n16 < nt; n16++) {
            float* c0 = C + n16 * 8;
            mma1(c0, al, bh[n16].x, bh[n16].y);
            mma1(c0 + 4, al, bh[n16].z, bh[n16].w);
        }
    }
}

template<int N, bool GB>
__device__ __forceinline__ void epi(char* sm, float* C, int t, int dA, int dB,
                                    const float* bias, const int* gix, const float* gbias) {
    const int nt = N / 32;
    int w = t >> 5, l = t & 31;
    int wr = (w & 3) * 16, wc = (w >> 2) * (N / 2);
    int lr = l >> 2, lc2 = 2 * (l & 3);
#pragma unroll
    for (int n16 = 0; n16 < nt; n16++)
#pragma unroll
    for (int nh = 0; nh < 2; nh++)
#pragma unroll
    for (int h = 0; h < 2; h++) {
        int row = wr + lr + h * 8;
        int col = wc + n16 * 16 + nh * 8 + lc2;
        float b0_, b1_;
        if (GB) {
            float2 bv = __ldg((const float2*)(gbias + gix[row] * 128 + col));
            b0_ = bv.x; b1_ = bv.y;
        } else { b0_ = bias[col]; b1_ = bias[col + 1]; }
        int ci = n16 * 8 + nh * 4 + h * 2;
        float v0 = sp(C[ci] + b0_), v1 = sp(C[ci + 1] + b1_);
        __half2 hb = __float22half2_rn(make_float2(v0, v1));
        float2 hf = __half22float2(hb);
        __half2 lb = __float22half2_rn(make_float2(v0 - hf.x, v1 - hf.y));
        char* p = sm + (col < 64 ? dA : dB) + (row * 72 + (col & 63)) * 2;
        *(uint32_t*)p = *(uint32_t*)&hb;
        *(uint32_t*)(p + PL) = *(uint32_t*)&lb;
    }
}

__device__ __forceinline__ void finep(char* sm, float* C, int t, int mode, int tile0,
        const float* feat, float* outP, const int* dIdx, const int* gix,
        float* accG, int* cg, const float* b2s) {
    int w = t >> 5, l = t & 31;
    int wr = (w & 3) * 16, wc = (w >> 2) * 32;
    int lr = l >> 2, lc2 = 2 * (l & 3);
    float2 f[8];
    float bb[8];
#pragma unroll
    for (int n16 = 0; n16 < 2; n16++)
#pragma unroll
    for (int nh = 0; nh < 2; nh++)
#pragma unroll
    for (int h = 0; h < 2; h++) {
        int row = wr + lr + h * 8;
        int col = wc + n16 * 16 + nh * 8 + lc2;
        int grow = tile0 + row;
        int idx = n16 * 4 + nh * 2 + h;
        if (!mode || grow < NN)
            f[idx] = __ldg((const float2*)(feat + (size_t)grow * 64 + col));
        bb[idx] = b2s[col];
    }
#pragma unroll
    for (int n16 = 0; n16 < 2; n16++)
#pragma unroll
    for (int nh = 0; nh < 2; nh++)
#pragma unroll
    for (int h = 0; h < 2; h++) {
        int row = wr + lr + h * 8;
        int col = wc + n16 * 16 + nh * 8 + lc2;
        int grow = tile0 + row;
        if (mode && grow >= NN) continue;
        int idx = n16 * 4 + nh * 2 + h;
        int ci = n16 * 8 + nh * 4 + h * 2;
        float v0 = sp(C[ci] + bb[idx]), v1 = sp(C[ci + 1] + b2s[col + 1]);
        *(float2*)(outP + (size_t)grow * 64 + col) = make_float2(v0 + f[idx].x, v1 + f[idx].y);
        int g = gix[row];
        atomicAdd(accG + g * 65 + col, v0); atomicAdd(accG + g * 65 + col + 1, v1);
        if (mode == 0) {
            int d = dIdx[row];
            redv2(g_accN + (size_t)d * 64 + col, v0, v1);
        }
        if ((w >> 2) == 0 && n16 == 0 && nh == 0 && (l & 3) == 0) {
            atomicAdd(cg + g, 1);
            if (mode == 0) atomicAdd(&g_cntN[dIdx[row]], 1);
        }
    }
}

__global__ __launch_bounds__(NT, 2) void k_mega(int mode, const float* __restrict__ feat,
        const int* __restrict__ srcI, const int* __restrict__ dstI, const int* __restrict__ batch,
        const float* __restrict__ beB, const float* __restrict__ b1e, const float* __restrict__ b2e,
        float* __restrict__ outP) {
    extern __shared__ char sm[];
    uint32_t sb = su32(sm);
    int t = threadIdx.x;
    int tile0 = blockIdx.x * 64;
    int* sIdx = (int*)(sm + B_IDX); int* dIdx = sIdx + 64; int* gix = dIdx + 64; int* cg = gix + 64;
    float* accG = (float*)(sm + B_ACCG);
    float* biasS = (float*)(sm + B_BIAS);
    const float* gbias = mode ? g_biasN0 : g_biasE0;

    if (t < 64) biasS[t] = mode ? 0.f : __ldg(beB + t);
    else if (t < 192) biasS[t] = __ldg(b1e + t - 64);
    else biasS[t] = __ldg(b2e + t - 192);
    if (t < 64) {
        if (mode == 0) {
            int e = tile0 + t, s = srcI[e];
            sIdx[t] = s; dIdx[t] = dstI[e]; gix[t] = batch[s];
        } else gix[t] = batch[min(tile0 + t, NN - 1)];
    }
    for (int i = t; i < 2080; i += NT) accG[i] = 0.f;
    if (t < 32) cg[t] = 0;
    __syncthreads();
    {
        int r = t >> 2, k0 = (t & 3) * 16;
        if (mode == 0) {
            gathSplit(sb, R0, sIdx[r], r, k0);
            gathSplit(sb, R1, dIdx[r], r, k0);
            cp_commit();
            gath16(feat + (size_t)(tile0 + r) * 64, sm + R2, r, k0, 1.f);
        } else {
            int ni = min(tile0 + r, NN - 1);
            gathSplit(sb, R0, ni, r, k0);
            cp_commit();
            float inv = 1.f / fmaxf((float)g_cntN[ni], 1.f);
            gath16(g_accN + (size_t)ni * 64, sm + R1, r, k0, inv);
        }
        cp_wait0();
    }
    __syncthreads();
    float C[32];
    const __half* WF = g_Wfrag;
    if (mode == 0) {
#pragma unroll
        for (int i = 0; i < 16; i++) C[i] = 0.f;
        mma_comp<64>(sb, R2, WF + 0, C, t);
        __syncthreads();
        epi<64,false>(sm, C, t, R2, R2, biasS, gix, gbias);
        __syncthreads();
#pragma unroll
        for (int i = 0; i < 32; i++) C[i] = 0.f;
        mma_comp<128>(sb, R0, WF + 4096, C, t);
        mma_comp<128>(sb, R1, WF + 12288, C, t);
        mma_comp<128>(sb, R2, WF + 20480, C, t);
        __syncthreads();
        epi<128,true>(sm, C, t, R0, R1, biasS, gix, gbias);
        __syncthreads();
#pragma unroll
        for (int i = 0; i < 32; i++) C[i] = 0.f;
        mma_comp<128>(sb, R0, WF + 28672, C, t);
        mma_comp<128>(sb, R1, WF + 36864, C, t);
        __syncthreads();
        epi<128,false>(sm, C, t, R0, R1, biasS + 64, gix, gbias);
        __syncthreads();
#pragma unroll
        for (int i = 0; i < 16; i++) C[i] = 0.f;
        mma_comp<64>(sb, R0, WF + 45056, C, t);
        mma_comp<64>(sb, R1, WF + 49152, C, t);
    } else {
#pragma unroll
        for (int i = 0; i < 32; i++) C[i] = 0.f;
        mma_comp<128>(sb, R0, WF + 53248, C, t);
        mma_comp<128>(sb, R1, WF + 61440, C, t);
        __syncthreads();
        epi<128,true>(sm, C, t, R0, R1, biasS, gix, gbias);
        __syncthreads();
#pragma unroll
        for (int i = 0; i < 32; i++) C[i] = 0.f;
        mma_comp<128>(sb, R0, WF + 69632, C, t);
        mma_comp<128>(sb, R1, WF + 77824, C, t);
        __syncthreads();
        epi<128,false>(sm, C, t, R0, R1, biasS + 64, gix, gbias);
        __syncthreads();
#pragma unroll
        for (int i = 0; i < 16; i++) C[i] = 0.f;
        mma_comp<64>(sb, R0, WF + 86016, C, t);
        mma_comp<64>(sb, R1, WF + 90112, C, t);
    }
    __syncthreads();
    finep(sm, C, t, mode, tile0, feat, outP, dIdx, gix, accG, cg, biasS + 192);
    __syncthreads();
    float* gacc = mode ? g_accNG : g_accEG;
    int* gcnt = mode ? g_cntNG : g_cntEG;
    for (int i = t; i < GG*DD; i += NT) atomicAdd(gacc + i, accG[(i >> 6) * 65 + (i & 63)]);
    if (t < 32) atomicAdd(gcnt + t, cg[t]);
}

// ---------------- prep kernels ----------------
__global__ void k_prepAll(const float* beW, const float* e0, const float* e1, const float* e2,
                          const float* n0, const float* n1, const float* n2) {
    int tid = blockIdx.x * blockDim.x + threadIdx.x, st = gridDim.x * blockDim.x;
    for (int x = tid; x < NN*DD; x += st) g_accN[x] = 0.f;
    for (int x = tid; x < NN; x += st) g_cntN[x] = 0;
    for (int x = tid; x < GG*DD; x += st) { g_accEG[x] = 0.f; g_accNG[x] = 0.f; }
    for (int x = tid; x < GG; x += st) { g_cntEG[x] = 0; g_cntNG[x] = 0; }
    const float* S[7] = {beW, e0, e1, e2, n0, n1, n2};
    const int K[7] = {64, 192, 128, 128, 128, 128, 128};
    const int Nw[7] = {64, 128, 128, 64, 128, 128, 64};
    const int ba[7] = {0, 4096, 28672, 45056, 53248, 69632, 86016};
    for (int L = 0; L < 7; L++) {
        int KK = K[L], Nc = Nw[L];
        const float* Sp = S[L];
        for (int idx = tid; idx < KK * Nc; idx += st) {
            int c = idx / (64 * Nc);
            int rch = idx - c * 64 * Nc;
            int f = rch >> 8;
            int wi = rch & 255;
            int l = wi >> 3;
            int r = (wi >> 1) & 3;
            int q = wi & 1;
            int i = f / (Nc / 16), j = f - i * (Nc / 16);
            int k = c * 64 + i * 16 + 2 * (l & 3) + (r & 1) * 8 + q;
            int n = j * 16 + (r >> 1) * 8 + (l >> 2);
            g_Wfrag[ba[L] + idx] = __float2half(Sp[k * Nc + n]);
        }
    }
}
__global__ void k_spostBias(const float* __restrict__ sf, const float* __restrict__ W,
                            const float* __restrict__ b,
                            const float* ceW0, const float* ceB0,
                            const float* cnW0, const float* cnB0) {
    __shared__ float sP[GG*DD];
    int t = threadIdx.x;
    {
        int g = t >> 3, jb = (t & 7) * 8;
        float a[8];
#pragma unroll
        for (int u = 0; u < 8; u++) a[u] = __ldg(b + jb + u);
        for (int k = 0; k < 64; k++) {
            float x = __ldg(sf + g*64 + k);
#pragma unroll
            for (int u = 0; u < 8; u++) a[u] += x * __ldg(W + k*64 + jb + u);
        }
#pragma unroll
        for (int u = 0; u < 8; u++) { float v = sp(a[u]); sP[g*64+jb+u] = v; g_sPost[g*64+jb+u] = v; }
    }
    __syncthreads();
    for (int i = t; i < 2 * GG * 128; i += 256) {
        int tab = i >> 12, r = i & 4095;
        int g = r >> 7, f = r & 127;
        const float* Wp = tab ? cnW0 : ceW0;
        int koff = tab ? 128 : 192;
        float a = tab ? __ldg(cnB0 + f) : __ldg(ceB0 + f);
        for (int k = 0; k < 64; k++)
            a += sP[g*64 + k] * __ldg(Wp + (koff + k) * 128 + f);
        (tab ? g_biasN0 : g_biasE0)[r] = a;
    }
}
__global__ __launch_bounds__(256) void k_npost(const float* __restrict__ nf,
                                               const float* __restrict__ W, const float* __restrict__ b) {
    extern __shared__ float smf[];
    float* xN = smf; float* wS = smf + 8192;
    int t = threadIdx.x, n0 = blockIdx.x * 128;
    {
        int r = t >> 1, h = t & 1;
        int row = min(n0 + r, NN - 1);
        const float4* p = (const float4*)(nf + (size_t)row * 64) + h * 8;
#pragma unroll
        for (int i = 0; i < 8; i++) {
            float4 v = p[i]; int k = h * 32 + i * 4;
            xN[(k+0)*128+r]=v.x; xN[(k+1)*128+r]=v.y; xN[(k+2)*128+r]=v.z; xN[(k+3)*128+r]=v.w;
        }
    }
    for (int i = t * 4; i < 4096; i += 1024) *(float4*)(wS + i) = *(const float4*)(W + i);
    __syncthreads();
    int e = t & 127, half = t >> 7, j0 = half * 32;
    float a[32];
#pragma unroll
    for (int q = 0; q < 8; q++) {
        float4 bv = *(const float4*)(b + j0 + q*4);
        a[q*4+0]=bv.x; a[q*4+1]=bv.y; a[q*4+2]=bv.z; a[q*4+3]=bv.w;
    }
#pragma unroll 2
    for (int k = 0; k < 64; k++) {
        float x = xN[k*128 + e];
#pragma unroll
        for (int q = 0; q < 8; q++) {
            float4 wv = *(const float4*)(wS + k*64 + j0 + q*4);
            a[q*4+0]+=x*wv.x; a[q*4+1]+=x*wv.y; a[q*4+2]+=x*wv.z; a[q*4+3]+=x*wv.w;
        }
    }
    int row = n0 + e;
    if (row < NN) {
        __half2* oh = (__half2*)(g_nPH + (size_t)row * 64 + j0);
        __half2* ol = (__half2*)(g_nPL + (size_t)row * 64 + j0);
#pragma unroll
        for (int q = 0; q < 16; q++) {
            float v0 = sp(a[q*2]), v1 = sp(a[q*2+1]);
            __half2 hb = __float22half2_rn(make_float2(v0, v1));
            float2 hf = __half22float2(hb);
            __half2 lb = __float22half2_rn(make_float2(v0 - hf.x, v1 - hf.y));
            oh[q] = hb; ol[q] = lb;
        }
    }
}
__global__ void k_state(const float* sf, const float* W0, const float* b0,
                        const float* W1, const float* b1, const float* W2, const float* b2, float* outS) {
    extern __shared__ float fs[];
    float* xs = fs; float* h1 = fs + 6144; float* hb = h1 + 4096;
    int t = threadIdx.x;
    for (int i = t; i < GG*DD; i += 256) {
        int g = i >> 6, k = i & 63;
        xs[g*192 + k] = g_sPost[i];
        xs[g*192 + 64 + k] = g_accEG[i] / fmaxf((float)g_cntEG[g], 1.f);
        xs[g*192 + 128 + k] = g_accNG[i] / fmaxf((float)g_cntNG[g], 1.f);
    }
    __syncthreads();
    for (int i = t; i < 4096; i += 256) {
        int g = i >> 7, f = i & 127;
        float a = __ldg(b0 + f);
        for (int k = 0; k < 192; k++) a += xs[g*192 + k] * __ldg(W0 + k*128 + f);
        h1[i] = sp(a);
    }
    __syncthreads();
    for (int i = t; i < 4096; i += 256) {
        int g = i >> 7, f = i & 127;
        float a = __ldg(b1 + f);
        for (int k = 0; k < 128; k++) a += h1[g*128 + k] * __ldg(W1 + k*128 + f);
        hb[i] = sp(a);
    }
    __syncthreads();
    for (int i = t; i < 2048; i += 256) {
        int g = i >> 6, f = i & 63;
        float a = __ldg(b2 + f);
        for (int k = 0; k < 128; k++) a += hb[g*128 + k] * __ldg(W2 + k*64 + f);
        outS[i] = sp(a) + __ldg(sf + i);
    }
}

extern "C" void kernel_launch(void* const* d_in, const int* in_sizes, int n_in,
                              void* d_out, int out_size) {
    const float* ef = (const float*)d_in[0];
    const float* nf = (const float*)d_in[1];
    const float* sf = (const float*)d_in[2];
    const int* eix = (const int*)d_in[3];
    const int* batch = (const int*)d_in[4];
    const float *beW=(const float*)d_in[5], *beB=(const float*)d_in[6];
    const float *bnW=(const float*)d_in[7], *bnB=(const float*)d_in[8];
    const float *bsW=(const float*)d_in[9], *bsB=(const float*)d_in[10];
    const float *ceW0=(const float*)d_in[11], *ceB0=(const float*)d_in[12];
    const float *ceW1=(const float*)d_in[13], *ceB1=(const float*)d_in[14];
    const float *ceW2=(const float*)d_in[15], *ceB2=(const float*)d_in[16];
    const float *cnW0=(const float*)d_in[17], *cnB0=(const float*)d_in[18];
    const float *cnW1=(const float*)d_in[19], *cnB1=(const float*)d_in[20];
    const float *cnW2=(const float*)d_in[21], *cnB2=(const float*)d_in[22];
    const float *csW0=(const float*)d_in[23], *csB0=(const float*)d_in[24];
    const float *csW1=(const float*)d_in[25], *csB1=(const float*)d_in[26];
    const float *csW2=(const float*)d_in[27], *csB2=(const float*)d_in[28];
    const int* srcI = eix; const int* dstI = eix + EE;
    float* outE = (float*)d_out;
    float* outN = outE + (size_t)EE * 64;
    float* outS = outN + (size_t)NN * 64;

    size_t smNP = (8192 + 4096) * sizeof(float);
    cudaFuncSetAttribute(k_npost, cudaFuncAttributeMaxDynamicSharedMemorySize, (int)smNP);
    cudaFuncSetAttribute(k_mega, cudaFuncAttributeMaxDynamicSharedMemorySize, SMEM_REQ);
    cudaFuncSetAttribute(k_state, cudaFuncAttributeMaxDynamicSharedMemorySize, 57344);

    k_prepAll<<<512, 512>>>(beW, ceW0, ceW1, ceW2, cnW0, cnW1, cnW2);
    k_spostBias<<<1, 256>>>(sf, bsW, bsB, ceW0, ceB0, cnW0, cnB0);
    k_npost<<<(NN + 127) / 128, 256, smNP>>>(nf, bnW, bnB);
    k_mega<<<EE / 64, NT, SMEM_REQ>>>(0, ef, srcI, dstI, batch, beB, ceB1, ceB2, outE);
    k_mega<<<(NN + 63) / 64, NT, SMEM_REQ>>>(1, nf, srcI, dstI, batch, beB, cnB1, cnB2, outN);
    k_state<<<1, 256, 57344>>>(sf, csW0, csB0, csW1, csB1, csW2, csB2, outS);
}

// round 15
// speedup vs baseline: 1.7383x; 1.1799x over previous
#include <cuda_runtime.h>
#include <cuda_fp16.h>
#include <math.h>
#include <stdint.h>

#define NN 50000
#define EE 800000
#define GG 32
#define DD 64
#define NT 256

// activation regions: [64 rows][72 el] fp16 single plane
#define R0 0
#define R1 9216
#define R2 18432
#define B_BIAS 27648
#define B_IDX  28672
#define B_ACCG 29568
#define SMEM_REQ 38912

__device__ __half g_nPH[NN*DD];   // nPost (fp16)
__device__ float g_sPost[GG*DD];
__device__ float g_accN[NN*DD];
__device__ int   g_cntN[NN];
__device__ float g_accEG[GG*DD]; __device__ int g_cntEG[GG];
__device__ float g_accNG[GG*DD]; __device__ int g_cntNG[GG];
__device__ float g_biasE0[GG*128];
__device__ float g_biasN0[GG*128];

// fragment-packed weights: per layer, chunks of K=64; per chunk
// [k16:4][n16:N/16][lane:32] x uint4 (= documented m16n8k16 B fragment order)
#define W_TOT 94208
__device__ __align__(16) __half g_Wfrag[W_TOT];

__device__ __forceinline__ float sp(float x) {
    return fmaxf(x, 0.0f) + __logf(1.0f + __expf(-fabsf(x)));
}
__device__ __forceinline__ uint32_t su32(const void* p) {
    uint32_t a;
    asm("{ .reg .u64 t; cvta.to.shared.u64 t, %1; cvt.u32.u64 %0, t; }" : "=r"(a) : "l"(p));
    return a;
}
__device__ __forceinline__ void ldsm4(uint32_t* r, uint32_t a) {
    asm volatile("ldmatrix.sync.aligned.m8n8.x4.shared.b16 {%0,%1,%2,%3},[%4];"
        : "=r"(r[0]), "=r"(r[1]), "=r"(r[2]), "=r"(r[3]) : "r"(a));
}
__device__ __forceinline__ void mma1(float* c, const uint32_t* a, uint32_t b0, uint32_t b1) {
    asm volatile("mma.sync.aligned.m16n8k16.row.col.f32.f16.f16.f32 "
        "{%0,%1,%2,%3},{%4,%5,%6,%7},{%8,%9},{%0,%1,%2,%3};"
        : "+f"(c[0]), "+f"(c[1]), "+f"(c[2]), "+f"(c[3])
        : "r"(a[0]), "r"(a[1]), "r"(a[2]), "r"(a[3]), "r"(b0), "r"(b1));
}
__device__ __forceinline__ void cp16(uint32_t d, const void* s) {
    asm volatile("cp.async.cg.shared.global [%0],[%1],16;" :: "r"(d), "l"(s));
}
__device__ __forceinline__ void cp_commit() { asm volatile("cp.async.commit_group;" ::: "memory"); }
__device__ __forceinline__ void cp_wait0() { asm volatile("cp.async.wait_group 0;" ::: "memory"); }
__device__ __forceinline__ void redv2(float* p, float v0, float v1) {
    asm volatile("red.global.add.v2.f32 [%0], {%1,%2};" :: "l"(p), "f"(v0), "f"(v1) : "memory");
}

__device__ __forceinline__ void st72(char* base, int row, int k0, const float* v) {
    unsigned hu[4];
#pragma unroll
    for (int i = 0; i < 4; i++) {
        __half2 hb = __float22half2_rn(make_float2(v[2*i], v[2*i+1]));
        hu[i] = *reinterpret_cast<unsigned*>(&hb);
    }
    *(uint4*)(base + (row * 72 + k0) * 2) = make_uint4(hu[0], hu[1], hu[2], hu[3]);
}
__device__ __forceinline__ void gath16(const float* rp, char* base, int r, int k0, float scl) {
    float v[8];
#pragma unroll
    for (int s2 = 0; s2 < 2; s2++) {
        float4 a = __ldg((const float4*)(rp + k0 + s2*8));
        float4 b = __ldg((const float4*)(rp + k0 + s2*8 + 4));
        v[0]=a.x*scl; v[1]=a.y*scl; v[2]=a.z*scl; v[3]=a.w*scl;
        v[4]=b.x*scl; v[5]=b.y*scl; v[6]=b.z*scl; v[7]=b.w*scl;
        st72(base, r, k0 + s2*8, v);
    }
}
// single-plane gather: 16 fp16 els via cp.async (no reg round-trip)
__device__ __forceinline__ void gathSplit(uint32_t sb, int reg, int row, int r, int k0) {
    const __half* ph = g_nPH + (size_t)row * 64 + k0;
    uint32_t d = sb + reg + (uint32_t)((r * 72 + k0) * 2);
    cp16(d, ph); cp16(d + 16, ph + 8);
}

// 8 warps: warp tile 16 rows x N/2 cols. single fp16 term: C += A*W
// B fragments loaded directly from global (L1-cached), pre-packed in mma order.
template<int N>
__device__ __forceinline__ void mma_comp(uint32_t sb, int actR, const __half* wf, float* C, int t) {
    const int nt = N / 32;
    int w = t >> 5, l = t & 31, lr = l & 15, lh = l >> 4;
    int wr = (w & 3) * 16, wcg = w >> 2;
    uint32_t aB = sb + actR + (uint32_t)(((wr + lr) * 72 + lh * 8) * 2);
    const uint4* wfb = (const uint4*)wf + (wcg * nt) * 32 + l;
#pragma unroll
    for (int k16 = 0; k16 < 4; k16++) {
        uint4 bh[nt];
#pragma unroll
        for (int n16 = 0; n16 < nt; n16++)
            bh[n16] = __ldg(wfb + (k16 * (N / 16) + n16) * 32);
        uint32_t ah[4];
        ldsm4(ah, aB + k16 * 32);
#pragma unroll
        for (int n16 = 0; n16 < nt; n16++) {
            float* c0 = C + n16 * 8;
            mma1(c0, ah, bh[n16].x, bh[n16].y);
            mma1(c0 + 4, ah, bh[n16].z, bh[n16].w);
        }
    }
}

template<int N, bool GB>
__device__ __forceinline__ void epi(char* sm, float* C, int t, int dA, int dB,
                                    const float* bias, const int* gix, const float* gbias) {
    const int nt = N / 32;
    int w = t >> 5, l = t & 31;
    int wr = (w & 3) * 16, wc = (w >> 2) * (N / 2);
    int lr = l >> 2, lc2 = 2 * (l & 3);
#pragma unroll
    for (int n16 = 0; n16 < nt; n16++)
#pragma unroll
    for (int nh = 0; nh < 2; nh++)
#pragma unroll
    for (int h = 0; h < 2; h++) {
        int row = wr + lr + h * 8;
        int col = wc + n16 * 16 + nh * 8 + lc2;
        float b0_, b1_;
        if (GB) {
            float2 bv = __ldg((const float2*)(gbias + gix[row] * 128 + col));
            b0_ = bv.x; b1_ = bv.y;
        } else { b0_ = bias[col]; b1_ = bias[col + 1]; }
        int ci = n16 * 8 + nh * 4 + h * 2;
        float v0 = sp(C[ci] + b0_), v1 = sp(C[ci + 1] + b1_);
        __half2 hb = __float22half2_rn(make_float2(v0, v1));
        char* p = sm + (col < 64 ? dA : dB) + (row * 72 + (col & 63)) * 2;
        *(uint32_t*)p = *(uint32_t*)&hb;
    }
}

__device__ __forceinline__ void finep(char* sm, float* C, int t, int mode, int tile0,
        const float* feat, float* outP, const int* dIdx, const int* gix,
        float* accG, int* cg, const float* b2s) {
    int w = t >> 5, l = t & 31;
    int wr = (w & 3) * 16, wc = (w >> 2) * 32;
    int lr = l >> 2, lc2 = 2 * (l & 3);
    float2 f[8];
    float bb[8];
#pragma unroll
    for (int n16 = 0; n16 < 2; n16++)
#pragma unroll
    for (int nh = 0; nh < 2; nh++)
#pragma unroll
    for (int h = 0; h < 2; h++) {
        int row = wr + lr + h * 8;
        int col = wc + n16 * 16 + nh * 8 + lc2;
        int grow = tile0 + row;
        int idx = n16 * 4 + nh * 2 + h;
        if (!mode || grow < NN)
            f[idx] = __ldg((const float2*)(feat + (size_t)grow * 64 + col));
        bb[idx] = b2s[col];
    }
#pragma unroll
    for (int n16 = 0; n16 < 2; n16++)
#pragma unroll
    for (int nh = 0; nh < 2; nh++)
#pragma unroll
    for (int h = 0; h < 2; h++) {
        int row = wr + lr + h * 8;
        int col = wc + n16 * 16 + nh * 8 + lc2;
        int grow = tile0 + row;
        if (mode && grow >= NN) continue;
        int idx = n16 * 4 + nh * 2 + h;
        int ci = n16 * 8 + nh * 4 + h * 2;
        float v0 = sp(C[ci] + bb[idx]), v1 = sp(C[ci + 1] + b2s[col + 1]);
        *(float2*)(outP + (size_t)grow * 64 + col) = make_float2(v0 + f[idx].x, v1 + f[idx].y);
        int g = gix[row];
        atomicAdd(accG + g * 65 + col, v0); atomicAdd(accG + g * 65 + col + 1, v1);
        if (mode == 0) {
            int d = dIdx[row];
            redv2(g_accN + (size_t)d * 64 + col, v0, v1);
        }
        if ((w >> 2) == 0 && n16 == 0 && nh == 0 && (l & 3) == 0) {
            atomicAdd(cg + g, 1);
            if (mode == 0) atomicAdd(&g_cntN[dIdx[row]], 1);
        }
    }
}

__global__ __launch_bounds__(NT, 2) void k_mega(int mode, const float* __restrict__ feat,
        const int* __restrict__ srcI, const int* __restrict__ dstI, const int* __restrict__ batch,
        const float* __restrict__ beB, const float* __restrict__ b1e, const float* __restrict__ b2e,
        float* __restrict__ outP) {
    extern __shared__ char sm[];
    uint32_t sb = su32(sm);
    int t = threadIdx.x;
    int tile0 = blockIdx.x * 64;
    int* sIdx = (int*)(sm + B_IDX); int* dIdx = sIdx + 64; int* gix = dIdx + 64; int* cg = gix + 64;
    float* accG = (float*)(sm + B_ACCG);
    float* biasS = (float*)(sm + B_BIAS);
    const float* gbias = mode ? g_biasN0 : g_biasE0;

    if (t < 64) biasS[t] = mode ? 0.f : __ldg(beB + t);
    else if (t < 192) biasS[t] = __ldg(b1e + t - 64);
    else biasS[t] = __ldg(b2e + t - 192);
    if (t < 64) {
        if (mode == 0) {
            int e = tile0 + t, s = srcI[e];
            sIdx[t] = s; dIdx[t] = dstI[e]; gix[t] = batch[s];
        } else gix[t] = batch[min(tile0 + t, NN - 1)];
    }
    for (int i = t; i < 2080; i += NT) accG[i] = 0.f;
    if (t < 32) cg[t] = 0;
    __syncthreads();
    {
        int r = t >> 2, k0 = (t & 3) * 16;
        if (mode == 0) {
            gathSplit(sb, R0, sIdx[r], r, k0);
            gathSplit(sb, R1, dIdx[r], r, k0);
            cp_commit();
            gath16(feat + (size_t)(tile0 + r) * 64, sm + R2, r, k0, 1.f);
        } else {
            int ni = min(tile0 + r, NN - 1);
            gathSplit(sb, R0, ni, r, k0);
            cp_commit();
            float inv = 1.f / fmaxf((float)g_cntN[ni], 1.f);
            gath16(g_accN + (size_t)ni * 64, sm + R1, r, k0, inv);
        }
        cp_wait0();
    }
    __syncthreads();
    float C[32];
    const __half* WF = g_Wfrag;
    if (mode == 0) {
#pragma unroll
        for (int i = 0; i < 16; i++) C[i] = 0.f;
        mma_comp<64>(sb, R2, WF + 0, C, t);
        __syncthreads();
        epi<64,false>(sm, C, t, R2, R2, biasS, gix, gbias);
        __syncthreads();
#pragma unroll
        for (int i = 0; i < 32; i++) C[i] = 0.f;
        mma_comp<128>(sb, R0, WF + 4096, C, t);
        mma_comp<128>(sb, R1, WF + 12288, C, t);
        mma_comp<128>(sb, R2, WF + 20480, C, t);
        __syncthreads();
        epi<128,true>(sm, C, t, R0, R1, biasS, gix, gbias);
        __syncthreads();
#pragma unroll
        for (int i = 0; i < 32; i++) C[i] = 0.f;
        mma_comp<128>(sb, R0, WF + 28672, C, t);
        mma_comp<128>(sb, R1, WF + 36864, C, t);
        __syncthreads();
        epi<128,false>(sm, C, t, R0, R1, biasS + 64, gix, gbias);
        __syncthreads();
#pragma unroll
        for (int i = 0; i < 16; i++) C[i] = 0.f;
        mma_comp<64>(sb, R0, WF + 45056, C, t);
        mma_comp<64>(sb, R1, WF + 49152, C, t);
    } else {
#pragma unroll
        for (int i = 0; i < 32; i++) C[i] = 0.f;
        mma_comp<128>(sb, R0, WF + 53248, C, t);
        mma_comp<128>(sb, R1, WF + 61440, C, t);
        __syncthreads();
        epi<128,true>(sm, C, t, R0, R1, biasS, gix, gbias);
        __syncthreads();
#pragma unroll
        for (int i = 0; i < 32; i++) C[i] = 0.f;
        mma_comp<128>(sb, R0, WF + 69632, C, t);
        mma_comp<128>(sb, R1, WF + 77824, C, t);
        __syncthreads();
        epi<128,false>(sm, C, t, R0, R1, biasS + 64, gix, gbias);
        __syncthreads();
#pragma unroll
        for (int i = 0; i < 16; i++) C[i] = 0.f;
        mma_comp<64>(sb, R0, WF + 86016, C, t);
        mma_comp<64>(sb, R1, WF + 90112, C, t);
    }
    __syncthreads();
    finep(sm, C, t, mode, tile0, feat, outP, dIdx, gix, accG, cg, biasS + 192);
    __syncthreads();
    float* gacc = mode ? g_accNG : g_accEG;
    int* gcnt = mode ? g_cntNG : g_cntEG;
    for (int i = t; i < GG*DD; i += NT) atomicAdd(gacc + i, accG[(i >> 6) * 65 + (i & 63)]);
    if (t < 32) atomicAdd(gcnt + t, cg[t]);
}

// ---------------- prep kernels ----------------
__global__ void k_prepAll(const float* beW, const float* e0, const float* e1, const float* e2,
                          const float* n0, const float* n1, const float* n2) {
    int tid = blockIdx.x * blockDim.x + threadIdx.x, st = gridDim.x * blockDim.x;
    for (int x = tid; x < NN*DD; x += st) g_accN[x] = 0.f;
    for (int x = tid; x < NN; x += st) g_cntN[x] = 0;
    for (int x = tid; x < GG*DD; x += st) { g_accEG[x] = 0.f; g_accNG[x] = 0.f; }
    for (int x = tid; x < GG; x += st) { g_cntEG[x] = 0; g_cntNG[x] = 0; }
    const float* S[7] = {beW, e0, e1, e2, n0, n1, n2};
    const int K[7] = {64, 192, 128, 128, 128, 128, 128};
    const int Nw[7] = {64, 128, 128, 64, 128, 128, 64};
    const int ba[7] = {0, 4096, 28672, 45056, 53248, 69632, 86016};
    for (int L = 0; L < 7; L++) {
        int KK = K[L], Nc = Nw[L];
        const float* Sp = S[L];
        for (int idx = tid; idx < KK * Nc; idx += st) {
            int c = idx / (64 * Nc);
            int rch = idx - c * 64 * Nc;
            int f = rch >> 8;
            int wi = rch & 255;
            int l = wi >> 3;
            int r = (wi >> 1) & 3;
            int q = wi & 1;
            int i = f / (Nc / 16), j = f - i * (Nc / 16);
            int k = c * 64 + i * 16 + 2 * (l & 3) + (r & 1) * 8 + q;
            int n = j * 16 + (r >> 1) * 8 + (l >> 2);
            g_Wfrag[ba[L] + idx] = __float2half(Sp[k * Nc + n]);
        }
    }
}
__global__ void k_spostBias(const float* __restrict__ sf, const float* __restrict__ W,
                            const float* __restrict__ b,
                            const float* ceW0, const float* ceB0,
                            const float* cnW0, const float* cnB0) {
    __shared__ float sP[GG*DD];
    int t = threadIdx.x;
    {
        int g = t >> 3, jb = (t & 7) * 8;
        float a[8];
#pragma unroll
        for (int u = 0; u < 8; u++) a[u] = __ldg(b + jb + u);
        for (int k = 0; k < 64; k++) {
            float x = __ldg(sf + g*64 + k);
#pragma unroll
            for (int u = 0; u < 8; u++) a[u] += x * __ldg(W + k*64 + jb + u);
        }
#pragma unroll
        for (int u = 0; u < 8; u++) { float v = sp(a[u]); sP[g*64+jb+u] = v; g_sPost[g*64+jb+u] = v; }
    }
    __syncthreads();
    for (int i = t; i < 2 * GG * 128; i += 256) {
        int tab = i >> 12, r = i & 4095;
        int g = r >> 7, f = r & 127;
        const float* Wp = tab ? cnW0 : ceW0;
        int koff = tab ? 128 : 192;
        float a = tab ? __ldg(cnB0 + f) : __ldg(ceB0 + f);
        for (int k = 0; k < 64; k++)
            a += sP[g*64 + k] * __ldg(Wp + (koff + k) * 128 + f);
        (tab ? g_biasN0 : g_biasE0)[r] = a;
    }
}
__global__ __launch_bounds__(256) void k_npost(const float* __restrict__ nf,
                                               const float* __restrict__ W, const float* __restrict__ b) {
    extern __shared__ float smf[];
    float* xN = smf; float* wS = smf + 8192;
    int t = threadIdx.x, n0 = blockIdx.x * 128;
    {
        int r = t >> 1, h = t & 1;
        int row = min(n0 + r, NN - 1);
        const float4* p = (const float4*)(nf + (size_t)row * 64) + h * 8;
#pragma unroll
        for (int i = 0; i < 8; i++) {
            float4 v = p[i]; int k = h * 32 + i * 4;
            xN[(k+0)*128+r]=v.x; xN[(k+1)*128+r]=v.y; xN[(k+2)*128+r]=v.z; xN[(k+3)*128+r]=v.w;
        }
    }
    for (int i = t * 4; i < 4096; i += 1024) *(float4*)(wS + i) = *(const float4*)(W + i);
    __syncthreads();
    int e = t & 127, half = t >> 7, j0 = half * 32;
    float a[32];
#pragma unroll
    for (int q = 0; q < 8; q++) {
        float4 bv = *(const float4*)(b + j0 + q*4);
        a[q*4+0]=bv.x; a[q*4+1]=bv.y; a[q*4+2]=bv.z; a[q*4+3]=bv.w;
    }
#pragma unroll 2
    for (int k = 0; k < 64; k++) {
        float x = xN[k*128 + e];
#pragma unroll
        for (int q = 0; q < 8; q++) {
            float4 wv = *(const float4*)(wS + k*64 + j0 + q*4);
            a[q*4+0]+=x*wv.x; a[q*4+1]+=x*wv.y; a[q*4+2]+=x*wv.z; a[q*4+3]+=x*wv.w;
        }
    }
    int row = n0 + e;
    if (row < NN) {
        __half2* oh = (__half2*)(g_nPH + (size_t)row * 64 + j0);
#pragma unroll
        for (int q = 0; q < 16; q++) {
            float v0 = sp(a[q*2]), v1 = sp(a[q*2+1]);
            oh[q] = __float22half2_rn(make_float2(v0, v1));
        }
    }
}
__global__ void k_state(const float* sf, const float* W0, const float* b0,
                        const float* W1, const float* b1, const float* W2, const float* b2, float* outS) {
    extern __shared__ float fs[];
    float* xs = fs; float* h1 = fs + 6144; float* hb = h1 + 4096;
    int t = threadIdx.x;
    for (int i = t; i < GG*DD; i += 256) {
        int g = i >> 6, k = i & 63;
        xs[g*192 + k] = g_sPost[i];
        xs[g*192 + 64 + k] = g_accEG[i] / fmaxf((float)g_cntEG[g], 1.f);
        xs[g*192 + 128 + k] = g_accNG[i] / fmaxf((float)g_cntNG[g], 1.f);
    }
    __syncthreads();
    for (int i = t; i < 4096; i += 256) {
        int g = i >> 7, f = i & 127;
        float a = __ldg(b0 + f);
        for (int k = 0; k < 192; k++) a += xs[g*192 + k] * __ldg(W0 + k*128 + f);
        h1[i] = sp(a);
    }
    __syncthreads();
    for (int i = t; i < 4096; i += 256) {
        int g = i >> 7, f = i & 127;
        float a = __ldg(b1 + f);
        for (int k = 0; k < 128; k++) a += h1[g*128 + k] * __ldg(W1 + k*128 + f);
        hb[i] = sp(a);
    }
    __syncthreads();
    for (int i = t; i < 2048; i += 256) {
        int g = i >> 6, f = i & 63;
        float a = __ldg(b2 + f);
        for (int k = 0; k < 128; k++) a += hb[g*128 + k] * __ldg(W2 + k*64 + f);
        outS[i] = sp(a) + __ldg(sf + i);
    }
}

extern "C" void kernel_launch(void* const* d_in, const int* in_sizes, int n_in,
                              void* d_out, int out_size) {
    const float* ef = (const float*)d_in[0];
    const float* nf = (const float*)d_in[1];
    const float* sf = (const float*)d_in[2];
    const int* eix = (const int*)d_in[3];
    const int* batch = (const int*)d_in[4];
    const float *beW=(const float*)d_in[5], *beB=(const float*)d_in[6];
    const float *bnW=(const float*)d_in[7], *bnB=(const float*)d_in[8];
    const float *bsW=(const float*)d_in[9], *bsB=(const float*)d_in[10];
    const float *ceW0=(const float*)d_in[11], *ceB0=(const float*)d_in[12];
    const float *ceW1=(const float*)d_in[13], *ceB1=(const float*)d_in[14];
    const float *ceW2=(const float*)d_in[15], *ceB2=(const float*)d_in[16];
    const float *cnW0=(const float*)d_in[17], *cnB0=(const float*)d_in[18];
    const float *cnW1=(const float*)d_in[19], *cnB1=(const float*)d_in[20];
    const float *cnW2=(const float*)d_in[21], *cnB2=(const float*)d_in[22];
    const float *csW0=(const float*)d_in[23], *csB0=(const float*)d_in[24];
    const float *csW1=(const float*)d_in[25], *csB1=(const float*)d_in[26];
    const float *csW2=(const float*)d_in[27], *csB2=(const float*)d_in[28];
    const int* srcI = eix; const int* dstI = eix + EE;
    float* outE = (float*)d_out;
    float* outN = outE + (size_t)EE * 64;
    float* outS = outN + (size_t)NN * 64;

    size_t smNP = (8192 + 4096) * sizeof(float);
    cudaFuncSetAttribute(k_npost, cudaFuncAttributeMaxDynamicSharedMemorySize, (int)smNP);
    cudaFuncSetAttribute(k_mega, cudaFuncAttributeMaxDynamicSharedMemorySize, SMEM_REQ);
    cudaFuncSetAttribute(k_state, cudaFuncAttributeMaxDynamicSharedMemorySize, 57344);

    k_prepAll<<<512, 512>>>(beW, ceW0, ceW1, ceW2, cnW0, cnW1, cnW2);
    k_spostBias<<<1, 256>>>(sf, bsW, bsB, ceW0, ceB0, cnW0, cnB0);
    k_npost<<<(NN + 127) / 128, 256, smNP>>>(nf, bnW, bnB);
    k_mega<<<EE / 64, NT, SMEM_REQ>>>(0, ef, srcI, dstI, batch, beB, ceB1, ceB2, outE);
    k_mega<<<(NN + 63) / 64, NT, SMEM_REQ>>>(1, nf, srcI, dstI, batch, beB, cnB1, cnB2, outN);
    k_state<<<1, 256, 57344>>>(sf, csW0, csB0, csW1, csB1, csW2, csB2, outS);
}